// round 3
// baseline (speedup 1.0000x reference)
#include <cuda_runtime.h>
#include <math.h>

// RMSD (Kabsch-aligned MSE), fused single kernel, f32x2 packed math.
// loss_b = Sxx + Syy - 2*(s0 + s1 + sign(det C)*s2)
// One warp per batch-pair (2 batches sequential), single resident wave.

constexpr int NB   = 8192;
constexpr int NP   = 512;
constexpr int WPB  = 8;
constexpr int NBLK = 512;              // 512 blocks * 8 warps = 4096 warps, 2 batches each
constexpr int HALF = NB / 2;           // 4096

__device__ double       g_partial[NBLK];
__device__ unsigned int g_count = 0;

using u64 = unsigned long long;

__device__ __forceinline__ u64 pk(float lo, float hi) {
    u64 r; asm("mov.b64 %0, {%1, %2};" : "=l"(r) : "f"(lo), "f"(hi)); return r;
}
__device__ __forceinline__ void fma2(u64& d, u64 a, u64 b) {
    asm("fma.rn.f32x2 %0, %1, %2, %0;" : "+l"(d) : "l"(a), "l"(b));
}
__device__ __forceinline__ void add2(u64& d, u64 a) {
    asm("add.rn.f32x2 %0, %1, %0;" : "+l"(d) : "l"(a));
}
__device__ __forceinline__ float hsum2(u64 v) {
    float lo, hi; asm("mov.b64 {%0, %1}, %2;" : "=f"(lo), "=f"(hi) : "l"(v));
    return lo + hi;
}

__device__ __forceinline__ float kabsch_loss(const float* fin)
{
    const float n = (float)NP;
    const float invn = 1.f / n;
    float mx[3], my[3];
#pragma unroll
    for (int d = 0; d < 3; d++) { mx[d] = fin[d] * invn; my[d] = fin[3 + d] * invn; }

    float C[3][3];
#pragma unroll
    for (int d = 0; d < 3; d++)
#pragma unroll
        for (int e = 0; e < 3; e++)
            C[d][e] = fin[8 + 3*d + e] - n * mx[d] * my[e];

    float sxx = fin[6] - n * (mx[0]*mx[0] + mx[1]*mx[1] + mx[2]*mx[2]);
    float syy = fin[7] - n * (my[0]*my[0] + my[1]*my[1] + my[2]*my[2]);

    float a00 = C[0][0]*C[0][0] + C[1][0]*C[1][0] + C[2][0]*C[2][0];
    float a11 = C[0][1]*C[0][1] + C[1][1]*C[1][1] + C[2][1]*C[2][1];
    float a22 = C[0][2]*C[0][2] + C[1][2]*C[1][2] + C[2][2]*C[2][2];
    float a01 = C[0][0]*C[0][1] + C[1][0]*C[1][1] + C[2][0]*C[2][1];
    float a02 = C[0][0]*C[0][2] + C[1][0]*C[1][2] + C[2][0]*C[2][2];
    float a12 = C[0][1]*C[0][2] + C[1][1]*C[1][2] + C[2][1]*C[2][2];

    float q  = (a00 + a11 + a22) * (1.f / 3.f);
    float p1 = a01*a01 + a02*a02 + a12*a12;
    float b00 = a00 - q, b11 = a11 - q, b22 = a22 - q;
    float p2 = b00*b00 + b11*b11 + b22*b22 + 2.f * p1;
    float p  = sqrtf(fmaxf(p2, 1e-30f) * (1.f / 6.f));
    float ip = 1.f / p;
    float detB = ( b00 * (b11*b22 - a12*a12)
                 - a01 * (a01*b22 - a12*a02)
                 + a02 * (a01*a12 - b11*a02) ) * (ip * ip * ip);
    float r = fminf(fmaxf(0.5f * detB, -1.f), 1.f);
    float phi = acosf(r) * (1.f / 3.f);
    float e0 = q + 2.f * p * cosf(phi);
    float e2 = q + 2.f * p * cosf(phi + 2.0943951023931953f);
    float e1 = 3.f * q - e0 - e2;

    float s0 = sqrtf(fmaxf(e0, 0.f));
    float s1 = sqrtf(fmaxf(e1, 0.f));
    float s2 = sqrtf(fmaxf(e2, 0.f));

    float detC = C[0][0]*(C[1][1]*C[2][2] - C[1][2]*C[2][1])
               - C[0][1]*(C[1][0]*C[2][2] - C[1][2]*C[2][0])
               + C[0][2]*(C[1][0]*C[2][1] - C[1][1]*C[2][0]);
    float sgn = (detC < 0.f) ? -1.f : 1.f;

    return sxx + syy - 2.f * (s0 + s1 + sgn * s2);
}

// Accumulate one pair of points (packed f32x2: lo=point A, hi=point B).
// xd[3], yd[3] packed per-dimension. 21 f32x2 ops.
__device__ __forceinline__ void acc_pair(u64* acc, const u64 xd[3], const u64 yd[3])
{
#pragma unroll
    for (int d = 0; d < 3; d++) {
        add2(acc[d],     xd[d]);
        add2(acc[3 + d], yd[d]);
        fma2(acc[6], xd[d], xd[d]);
        fma2(acc[7], yd[d], yd[d]);
#pragma unroll
        for (int e = 0; e < 3; e++)
            fma2(acc[8 + 3*d + e], xd[d], yd[e]);
    }
}

__global__ __launch_bounds__(256)
void rmsd_fused_kernel(const float4* __restrict__ x4, const float4* __restrict__ y4,
                       float* __restrict__ out)
{
    const int w    = threadIdx.x >> 5;
    const int lane = threadIdx.x & 31;
    const int gw   = blockIdx.x * WPB + w;   // 0..4095

    double local_loss = 0.0;

#pragma unroll 1
    for (int bi = 0; bi < 2; bi++) {
        const int b = gw + bi * HALF;
        const size_t base = (size_t)b * 384;   // 384 float4 per batch

        u64 acc[17];
#pragma unroll
        for (int i = 0; i < 17; i++) acc[i] = 0ull;

#pragma unroll
        for (int k = 0; k < 4; k++) {
            const int g = k * 32 + lane;       // 4-point group index
            const float4* xp = x4 + base + 3 * g;
            const float4* yp = y4 + base + 3 * g;
            float4 xa = xp[0], xb = xp[1], xc = xp[2];
            float4 ya = yp[0], yb = yp[1], yc = yp[2];

            // pair (p0,p1): p0=(xa.x,xa.y,xa.z) p1=(xa.w,xb.x,xb.y)
            {
                u64 xd[3] = { pk(xa.x, xa.w), pk(xa.y, xb.x), pk(xa.z, xb.y) };
                u64 yd[3] = { pk(ya.x, ya.w), pk(ya.y, yb.x), pk(ya.z, yb.y) };
                acc_pair(acc, xd, yd);
            }
            // pair (p2,p3): p2=(xb.z,xb.w,xc.x) p3=(xc.y,xc.z,xc.w)
            {
                u64 xd[3] = { pk(xb.z, xc.y), pk(xb.w, xc.z), pk(xc.x, xc.w) };
                u64 yd[3] = { pk(yb.z, yc.y), pk(yb.w, yc.z), pk(yc.x, yc.w) };
                acc_pair(acc, xd, yd);
            }
        }

        float v[17];
#pragma unroll
        for (int i = 0; i < 17; i++) v[i] = hsum2(acc[i]);

#pragma unroll
        for (int i = 0; i < 17; i++) {
#pragma unroll
            for (int o = 16; o > 0; o >>= 1)
                v[i] += __shfl_down_sync(0xffffffffu, v[i], o);
        }

        if (lane == 0) local_loss += (double)kabsch_loss(v);
    }

    __shared__ double warp_loss[WPB];
    __shared__ int    is_last;
    if (lane == 0) warp_loss[w] = local_loss;
    __syncthreads();

    if (threadIdx.x == 0) {
        double s = 0.0;
#pragma unroll
        for (int i = 0; i < WPB; i++) s += warp_loss[i];
        g_partial[blockIdx.x] = s;
        __threadfence();
        unsigned done = atomicAdd(&g_count, 1u);
        is_last = (done == NBLK - 1) ? 1 : 0;
    }
    __syncthreads();

    if (is_last) {
        __threadfence();
        const int t = threadIdx.x;
        volatile double* gp = g_partial;
        double s = 0.0;
#pragma unroll
        for (int i = 0; i < NBLK / 256; i++) s += gp[t + i * 256];

#pragma unroll
        for (int o = 16; o > 0; o >>= 1)
            s += __shfl_down_sync(0xffffffffu, s, o);

        __shared__ double sm[8];
        if (lane == 0) sm[w] = s;
        __syncthreads();
        if (t == 0) {
            double tot = 0.0;
#pragma unroll
            for (int i = 0; i < 8; i++) tot += sm[i];
            out[0] = (float)(tot / ((double)NB * (double)NP * 3.0));
            g_count = 0;   // reset for graph replay
        }
    }
}

extern "C" void kernel_launch(void* const* d_in, const int* in_sizes, int n_in,
                              void* d_out, int out_size)
{
    const float4* inp = (const float4*)d_in[0];
    const float4* tgt = (const float4*)d_in[1];
    float* out = (float*)d_out;

    rmsd_fused_kernel<<<NBLK, 256>>>(inp, tgt, out);
}

// round 4
// speedup vs baseline: 1.1641x; 1.1641x over previous
#include <cuda_runtime.h>
#include <math.h>

// RMSD (Kabsch-aligned MSE), fused single kernel.
// Coalesced LDG.128 -> smem (warp-local tile transpose) -> conflict-free LDS.32.
// One warp per batch. loss_b = Sxx + Syy - 2*(s0 + s1 + sign(det C)*s2).

constexpr int NB   = 8192;
constexpr int NP   = 512;
constexpr int WPB  = 8;
constexpr int NBLK = NB / WPB;   // 1024

__device__ double       g_partial[NBLK];
__device__ unsigned int g_count = 0;

__device__ __forceinline__ float kabsch_loss(const float* fin)
{
    const float n = (float)NP;
    const float invn = 1.f / n;
    float mx[3], my[3];
#pragma unroll
    for (int d = 0; d < 3; d++) { mx[d] = fin[d] * invn; my[d] = fin[3 + d] * invn; }

    float C[3][3];
#pragma unroll
    for (int d = 0; d < 3; d++)
#pragma unroll
        for (int e = 0; e < 3; e++)
            C[d][e] = fin[8 + 3*d + e] - n * mx[d] * my[e];

    float sxx = fin[6] - n * (mx[0]*mx[0] + mx[1]*mx[1] + mx[2]*mx[2]);
    float syy = fin[7] - n * (my[0]*my[0] + my[1]*my[1] + my[2]*my[2]);

    float a00 = C[0][0]*C[0][0] + C[1][0]*C[1][0] + C[2][0]*C[2][0];
    float a11 = C[0][1]*C[0][1] + C[1][1]*C[1][1] + C[2][1]*C[2][1];
    float a22 = C[0][2]*C[0][2] + C[1][2]*C[1][2] + C[2][2]*C[2][2];
    float a01 = C[0][0]*C[0][1] + C[1][0]*C[1][1] + C[2][0]*C[2][1];
    float a02 = C[0][0]*C[0][2] + C[1][0]*C[1][2] + C[2][0]*C[2][2];
    float a12 = C[0][1]*C[0][2] + C[1][1]*C[1][2] + C[2][1]*C[2][2];

    float q  = (a00 + a11 + a22) * (1.f / 3.f);
    float p1 = a01*a01 + a02*a02 + a12*a12;
    float b00 = a00 - q, b11 = a11 - q, b22 = a22 - q;
    float p2 = b00*b00 + b11*b11 + b22*b22 + 2.f * p1;
    float p  = sqrtf(fmaxf(p2, 1e-30f) * (1.f / 6.f));
    float ip = 1.f / p;
    float detB = ( b00 * (b11*b22 - a12*a12)
                 - a01 * (a01*b22 - a12*a02)
                 + a02 * (a01*a12 - b11*a02) ) * (ip * ip * ip);
    float r = fminf(fmaxf(0.5f * detB, -1.f), 1.f);
    float phi = acosf(r) * (1.f / 3.f);
    float e0 = q + 2.f * p * cosf(phi);
    float e2 = q + 2.f * p * cosf(phi + 2.0943951023931953f);
    float e1 = 3.f * q - e0 - e2;

    float s0 = sqrtf(fmaxf(e0, 0.f));
    float s1 = sqrtf(fmaxf(e1, 0.f));
    float s2 = sqrtf(fmaxf(e2, 0.f));

    float detC = C[0][0]*(C[1][1]*C[2][2] - C[1][2]*C[2][1])
               - C[0][1]*(C[1][0]*C[2][2] - C[1][2]*C[2][0])
               + C[0][2]*(C[1][0]*C[2][1] - C[1][1]*C[2][0]);
    float sgn = (detC < 0.f) ? -1.f : 1.f;

    return sxx + syy - 2.f * (s0 + s1 + sgn * s2);
}

// Tile geometry: 128 points = 1536 B = 96 float4 per tensor per tile, 4 tiles/batch.
// smem per warp: 2 tensors * 2 buffers * 96 float4 = 6 KB -> 48 KB/block.
__global__ __launch_bounds__(256)
void rmsd_fused_kernel(const float4* __restrict__ x4, const float4* __restrict__ y4,
                       float* __restrict__ out)
{
    __shared__ float4 smem[WPB][2][2][96];   // [warp][buf][tensor 0=x 1=y][96]

    const int w    = threadIdx.x >> 5;
    const int lane = threadIdx.x & 31;
    const int b    = blockIdx.x * WPB + w;
    const size_t base = (size_t)b * 384;     // float4 per batch

    float v[17];
#pragma unroll
    for (int i = 0; i < 17; i++) v[i] = 0.f;

    // Prologue: load tile 0 (coalesced: lane-contiguous float4)
    float4 xr[3], yr[3];
#pragma unroll
    for (int m = 0; m < 3; m++) {
        xr[m] = x4[base + m * 32 + lane];
        yr[m] = y4[base + m * 32 + lane];
    }
#pragma unroll
    for (int m = 0; m < 3; m++) {
        smem[w][0][0][m * 32 + lane] = xr[m];
        smem[w][0][1][m * 32 + lane] = yr[m];
    }
    __syncwarp();

#pragma unroll
    for (int tile = 0; tile < 4; tile++) {
        const int buf = tile & 1;

        // Issue next tile's loads early (overlap DRAM latency with compute)
        if (tile < 3) {
            const size_t tb = base + (size_t)(tile + 1) * 96;
#pragma unroll
            for (int m = 0; m < 3; m++) {
                xr[m] = x4[tb + m * 32 + lane];
                yr[m] = y4[tb + m * 32 + lane];
            }
        }

        // Compute 4 points from smem (LDS.32, 12B stride: conflict-free)
        const float* sx = reinterpret_cast<const float*>(smem[w][buf][0]);
        const float* sy = reinterpret_cast<const float*>(smem[w][buf][1]);
#pragma unroll
        for (int c = 0; c < 4; c++) {
            const int p = c * 32 + lane;
            float X[3] = { sx[3*p], sx[3*p + 1], sx[3*p + 2] };
            float Y[3] = { sy[3*p], sy[3*p + 1], sy[3*p + 2] };
#pragma unroll
            for (int d = 0; d < 3; d++) {
                v[d]     += X[d];
                v[3 + d] += Y[d];
                v[6]     += X[d] * X[d];
                v[7]     += Y[d] * Y[d];
#pragma unroll
                for (int e = 0; e < 3; e++)
                    v[8 + 3*d + e] += X[d] * Y[e];
            }
        }

        if (tile < 3) {
            __syncwarp();   // everyone done reading buf^1 from the previous round
            const int nbuf = buf ^ 1;
#pragma unroll
            for (int m = 0; m < 3; m++) {
                smem[w][nbuf][0][m * 32 + lane] = xr[m];
                smem[w][nbuf][1][m * 32 + lane] = yr[m];
            }
            __syncwarp();
        }
    }

    // Warp tree-reduce 17 values
#pragma unroll
    for (int i = 0; i < 17; i++) {
#pragma unroll
        for (int o = 16; o > 0; o >>= 1)
            v[i] += __shfl_down_sync(0xffffffffu, v[i], o);
    }

    __shared__ float warp_loss[WPB];
    __shared__ int   is_last;
    if (lane == 0) warp_loss[w] = kabsch_loss(v);
    __syncthreads();

    if (threadIdx.x == 0) {
        double s = 0.0;
#pragma unroll
        for (int i = 0; i < WPB; i++) s += (double)warp_loss[i];
        g_partial[blockIdx.x] = s;
        __threadfence();
        unsigned done = atomicAdd(&g_count, 1u);
        is_last = (done == NBLK - 1) ? 1 : 0;
    }
    __syncthreads();

    if (is_last) {
        __threadfence();
        const int t = threadIdx.x;
        volatile double* gp = g_partial;
        double s = 0.0;
#pragma unroll
        for (int i = 0; i < NBLK / 256; i++) s += gp[t + i * 256];

#pragma unroll
        for (int o = 16; o > 0; o >>= 1)
            s += __shfl_down_sync(0xffffffffu, s, o);

        __shared__ double sm[8];
        if (lane == 0) sm[w] = s;
        __syncthreads();
        if (t == 0) {
            double tot = 0.0;
#pragma unroll
            for (int i = 0; i < 8; i++) tot += sm[i];
            out[0] = (float)(tot / ((double)NB * (double)NP * 3.0));
            g_count = 0;   // reset for graph replay
        }
    }
}

extern "C" void kernel_launch(void* const* d_in, const int* in_sizes, int n_in,
                              void* d_out, int out_size)
{
    const float4* inp = (const float4*)d_in[0];
    const float4* tgt = (const float4*)d_in[1];
    float* out = (float*)d_out;

    rmsd_fused_kernel<<<NBLK, 256>>>(inp, tgt, out);
}